// round 15
// baseline (speedup 1.0000x reference)
#include <cuda_runtime.h>
#include <math.h>

#define HH    512
#define NIMG  72          // B(8)*M(3)*W(3); wavelength = img % 3
#define NWL   3
#define NLAY  5
#define TWO_PI 6.2831853071795864769f

#define LPLANE 528        // row-kernel per-line exchange plane (float2)
#define CPLANE 529        // k_col per-column plane (odd float2 stride)
#define CT     8          // columns per col tile
#define TPB    4          // tiles per col block (pipelined)

// Storage-slot -> spectral-index map of the 16x32 warp-group FFT.
#define KMAP(s) (((s) & 15) | ((((s) >> 8) & 1) << 4) | ((((s) >> 4) & 15) << 5))

// -------- precomputed tables --------
__device__ float2 d_HL[NWL * HH * HH];    // exp(i kz zL) / 512
__device__ float2 d_HLD[NWL * HH * HH];   // exp(i kz (zL+zD)) / 512 (merged; cancelled pair gain 512)
__device__ float2 d_expP[NLAY * NWL * HH * HH];

__device__ __forceinline__ float2 cmulf(float2 a, float2 b) {
    return make_float2(a.x * b.x - a.y * b.y, a.x * b.y + a.y * b.x);
}
template <int SGN>
__device__ __forceinline__ float2 muli(float2 z) {
    return (SGN > 0) ? make_float2(-z.y, z.x) : make_float2(z.y, -z.x);
}
__device__ __forceinline__ int taud(int k) { return (k < 8) ? 2 * k : 2 * (k - 8) + 1; }
__device__ __forceinline__ int alp(int i) {
    return ((i & 7) << 2) | (((i >> 3) & 1) << 1) | (i >> 4);
}

__device__ __forceinline__ void cpasync8(void* smem, const void* g) {
    unsigned s = (unsigned)__cvta_generic_to_shared(smem);
    asm volatile("cp.async.ca.shared.global [%0], [%1], 8;" :: "r"(s), "l"(g) : "memory");
}
__device__ __forceinline__ void cpcommit() {
    asm volatile("cp.async.commit_group;" ::: "memory");
}
__device__ __forceinline__ void cpwait0() {
    asm volatile("cp.async.wait_group 0;" ::: "memory");
}
__device__ __forceinline__ void cpwait1() {
    asm volatile("cp.async.wait_group 1;" ::: "memory");
}

// natural-order 8-point DFT (in place)
template <int SGN>
__device__ __forceinline__ void dft8(float2 v[8]) {
    const float C = 0.70710678118654752f;
    const float sg = (float)SGN;
    float2 t0 = make_float2(v[0].x + v[4].x, v[0].y + v[4].y);
    float2 t1 = make_float2(v[0].x - v[4].x, v[0].y - v[4].y);
    float2 t2 = make_float2(v[2].x + v[6].x, v[2].y + v[6].y);
    float2 t3 = make_float2(v[2].x - v[6].x, v[2].y - v[6].y);
    float2 u0 = make_float2(v[1].x + v[5].x, v[1].y + v[5].y);
    float2 u1 = make_float2(v[1].x - v[5].x, v[1].y - v[5].y);
    float2 u2 = make_float2(v[3].x + v[7].x, v[3].y + v[7].y);
    float2 u3 = make_float2(v[3].x - v[7].x, v[3].y - v[7].y);
    float2 it3 = muli<SGN>(t3);
    float2 iu3 = muli<SGN>(u3);
    float2 E0 = make_float2(t0.x + t2.x, t0.y + t2.y);
    float2 E2 = make_float2(t0.x - t2.x, t0.y - t2.y);
    float2 E1 = make_float2(t1.x + it3.x, t1.y + it3.y);
    float2 E3 = make_float2(t1.x - it3.x, t1.y - it3.y);
    float2 O0 = make_float2(u0.x + u2.x, u0.y + u2.y);
    float2 O2 = make_float2(u0.x - u2.x, u0.y - u2.y);
    float2 O1 = make_float2(u1.x + iu3.x, u1.y + iu3.y);
    float2 O3 = make_float2(u1.x - iu3.x, u1.y - iu3.y);
    float2 w1o = make_float2(C * (O1.x - sg * O1.y), C * (O1.y + sg * O1.x));
    float2 w2o = muli<SGN>(O2);
    float2 w3o = make_float2(-C * (O3.x + sg * O3.y), C * (sg * O3.x - O3.y));
    v[0] = make_float2(E0.x + O0.x, E0.y + O0.y);
    v[4] = make_float2(E0.x - O0.x, E0.y - O0.y);
    v[1] = make_float2(E1.x + w1o.x, E1.y + w1o.y);
    v[5] = make_float2(E1.x - w1o.x, E1.y - w1o.y);
    v[2] = make_float2(E2.x + w2o.x, E2.y + w2o.y);
    v[6] = make_float2(E2.x - w2o.x, E2.y - w2o.y);
    v[3] = make_float2(E3.x + w3o.x, E3.y + w3o.y);
    v[7] = make_float2(E3.x - w3o.x, E3.y - w3o.y);
}

#define CC16_1 0.92387953251128674f
#define CC16_2 0.70710678118654752f
#define CC16_3 0.38268343236508977f

template <int SGN>
__device__ __forceinline__ void dit16(float2 v[16]) {
    const float CC[8] = {1.f, CC16_1, CC16_2, CC16_3, 0.f, -CC16_3, -CC16_2, -CC16_1};
    const float SS[8] = {0.f, CC16_3, CC16_2, CC16_1, 1.f, CC16_1, CC16_2, CC16_3};
    dft8<SGN>(v);
    dft8<SGN>(v + 8);
#pragma unroll
    for (int r = 0; r < 8; r++) {
        float2 w = make_float2(CC[r], (float)SGN * SS[r]);
        float2 t = cmulf(v[8 + r], w);
        v[8 + r] = make_float2(v[r].x - t.x, v[r].y - t.y);
        v[r]     = make_float2(v[r].x + t.x, v[r].y + t.y);
    }
}

template <int SGN>
__device__ __forceinline__ void dif16(float2 v[16]) {
    const float CC[8] = {1.f, CC16_1, CC16_2, CC16_3, 0.f, -CC16_3, -CC16_2, -CC16_1};
    const float SS[8] = {0.f, CC16_3, CC16_2, CC16_1, 1.f, CC16_1, CC16_2, CC16_3};
#pragma unroll
    for (int r = 0; r < 8; r++) {
        float2 a = v[r], b = v[8 + r];
        v[r] = make_float2(a.x + b.x, a.y + b.y);
        float2 d = make_float2(a.x - b.x, a.y - b.y);
        float2 w = make_float2(CC[r], (float)SGN * SS[r]);
        v[8 + r] = cmulf(d, w);
    }
    dft8<SGN>(v);
    dft8<SGN>(v + 8);
}

#define C32_1 0.98078528040323044f
#define C32_2 0.92387953251128674f
#define C32_3 0.83146961230254524f
#define C32_4 0.70710678118654752f
#define C32_5 0.55557023301960222f
#define C32_6 0.38268343236508977f
#define C32_7 0.19509032201612827f

template <int SGN>
__device__ __forceinline__ void dit32(float2 v[32]) {
    const float C[16] = {1.f, C32_1, C32_2, C32_3, C32_4, C32_5, C32_6, C32_7,
                         0.f, -C32_7, -C32_6, -C32_5, -C32_4, -C32_3, -C32_2, -C32_1};
    const float S[16] = {0.f, C32_7, C32_6, C32_5, C32_4, C32_3, C32_2, C32_1,
                         1.f, C32_1, C32_2, C32_3, C32_4, C32_5, C32_6, C32_7};
    dit16<SGN>(v);
    dit16<SGN>(v + 16);
#pragma unroll
    for (int r = 0; r < 16; r++) {
        float2 w = make_float2(C[r], (float)SGN * S[r]);
        float2 t = cmulf(v[16 + r], w);
        v[16 + r] = make_float2(v[r].x - t.x, v[r].y - t.y);
        v[r]      = make_float2(v[r].x + t.x, v[r].y + t.y);
    }
}

template <int SGN>
__device__ __forceinline__ void dif32(float2 v[32]) {
    const float C[16] = {1.f, C32_1, C32_2, C32_3, C32_4, C32_5, C32_6, C32_7,
                         0.f, -C32_7, -C32_6, -C32_5, -C32_4, -C32_3, -C32_2, -C32_1};
    const float S[16] = {0.f, C32_7, C32_6, C32_5, C32_4, C32_3, C32_2, C32_1,
                         1.f, C32_1, C32_2, C32_3, C32_4, C32_5, C32_6, C32_7};
#pragma unroll
    for (int r = 0; r < 16; r++) {
        float2 a = v[r], b = v[16 + r];
        v[r] = make_float2(a.x + b.x, a.y + b.y);
        float2 d = make_float2(a.x - b.x, a.y - b.y);
        float2 w = make_float2(C[r], (float)SGN * S[r]);
        v[16 + r] = cmulf(d, w);
    }
    dif16<SGN>(v);
    dif16<SGN>(v + 16);
}

template <int SGN>
__device__ __forceinline__ void twid_alp(float2 v[32], int t) {
    float s, c;
    __sincosf((float)SGN * TWO_PI * (float)t * (1.0f / 512.0f), &s, &c);
    float2 w1 = make_float2(c, s);
    float2 w2 = cmulf(w1, w1);
    float2 w3 = cmulf(w2, w1);
    float2 w4 = cmulf(w2, w2);
    float2 bases[4];
    bases[0] = make_float2(1.f, 0.f); bases[1] = w2; bases[2] = w1; bases[3] = w3;
#pragma unroll
    for (int g = 0; g < 4; g++) {
        float2 tw = bases[g];
#pragma unroll
        for (int k = 0; k < 8; k++) {
            int r = g * 8 + k;
            if (!(g == 0 && k == 0)) v[r] = cmulf(v[r], tw);
            if (k < 7) tw = cmulf(tw, w4);
        }
    }
}

template <int SGN>
__device__ __forceinline__ void twid_tau(float2* v, int m) {
    float s, c;
    __sincosf((float)SGN * TWO_PI * (float)m * (1.0f / 512.0f), &s, &c);
    float2 w1 = make_float2(c, s);
    float2 w2 = cmulf(w1, w1);
    float2 tw = w2;
#pragma unroll
    for (int k = 1; k < 8; k++) { v[k] = cmulf(v[k], tw); tw = cmulf(tw, w2); }
    tw = w1;
#pragma unroll
    for (int k = 8; k < 16; k++) { v[k] = cmulf(v[k], tw); tw = cmulf(tw, w2); }
}

// forward 512-pt group FFT (16 threads, 1 exchange)
__device__ __forceinline__ void gfwd(float2 v[32], float2* pl, int t) {
    dif32<-1>(v);
    twid_alp<-1>(v, t);
    __syncwarp();
#pragma unroll
    for (int r = 0; r < 32; r++) pl[alp(r) + 33 * t] = v[r];
    __syncwarp();
#pragma unroll
    for (int k = 0; k < 16; k++) v[k]      = pl[t      + 33 * taud(k)];
#pragma unroll
    for (int k = 0; k < 16; k++) v[16 + k] = pl[t + 16 + 33 * taud(k)];
    dit16<-1>(v);
    dit16<-1>(v + 16);
}

// inverse 512-pt group FFT (unnormalized)
__device__ __forceinline__ void ginv(float2 v[32], float2* pl, int t) {
    dif16<1>(v);
    dif16<1>(v + 16);
    twid_tau<1>(v, t);
    twid_tau<1>(v + 16, t + 16);
    __syncwarp();
#pragma unroll
    for (int k = 0; k < 16; k++) pl[t      + 33 * taud(k)] = v[k];
#pragma unroll
    for (int k = 0; k < 16; k++) pl[t + 16 + 33 * taud(k)] = v[16 + k];
    __syncwarp();
#pragma unroll
    for (int r = 0; r < 32; r++) v[r] = pl[alp(r) + 33 * t];
    dit32<1>(v);
}

// ---------------- init kernels ----------------

__global__ void __launch_bounds__(256) k_initH() {
    int idx = blockIdx.x * 256 + threadIdx.x;
    if (idx >= NWL * HH * HH) return;
    int w = idx / (HH * HH);
    int xs = (idx >> 9) & 511;
    int j = idx & 511;
    int r = KMAP(xs);
    int c = KMAP(j);
    const float wls[3] = {5.32e-07f, 6.33e-07f, 8.5e-07f};
    const float TW = TWO_PI;
    float mr = (float)((r < 256) ? r : r - 512);
    float mc = (float)((c < 256) ? c : c - 512);
    double invnd = 1.0 / (512.0 * 8e-06);
    float fr = (float)((double)mr * invnd);
    float fc = (float)((double)mc * invnd);
    float kx = __fmul_rn(TW, fr);
    float ky = __fmul_rn(TW, fc);
    float kk = __fdiv_rn(TW, wls[w]);
    float arg = __fsub_rn(__fsub_rn(__fmul_rn(kk, kk), __fmul_rn(kx, kx)),
                          __fmul_rn(ky, ky));
    const float SL  = 1.0f / 512.0f;
    const float SLD = 1.0f / 512.0f;   // merged pass absorbs the cancelled pair's gain 512
    float2 hl, hld;
    if (arg >= 0.0f) {
        float kz = __fsqrt_rn(arg);
        float thL = __fmul_rn(kz, 0.03f);
        float thD = __fmul_rn(kz, 0.1f);
        double sl, cl, sd, cd;
        sincos((double)thL, &sl, &cl);
        sincos((double)thD, &sd, &cd);
        double pr = cl * cd - sl * sd;
        double pi = cl * sd + sl * cd;
        hl  = make_float2((float)cl * SL, (float)sl * SL);
        hld = make_float2((float)pr * SLD, (float)pi * SLD);
    } else {
        float a = __fsqrt_rn(-arg);
        float eL = expf(-__fmul_rn(a, 0.03f));
        float eD = expf(-__fmul_rn(a, 0.1f));
        hl  = make_float2(eL * SL, 0.0f);
        hld = make_float2(eL * eD * SLD, 0.0f);
    }
    d_HL[idx]  = hl;    // arg symmetric in (r,c) => no transpose needed
    d_HLD[idx] = hld;
}

__global__ void __launch_bounds__(256) k_initP(const float* __restrict__ pm) {
    int idx = blockIdx.x * 256 + threadIdx.x;
    if (idx >= NLAY * NWL * HH * HH) return;
    float p = pm[idx];
    float s, c;
    __sincosf(p, &s, &c);
    int layer = idx / (NWL * HH * HH);
    float sc = (layer == 0) ? 1.0f : (1.0f / 512.0f);
    d_expP[idx] = make_float2(c * sc, s * sc);
}

// ---------------- row kernels: 16 threads/line, 16 lines/block ----------------

__global__ void __launch_bounds__(256, 2) k_first(const float* __restrict__ xr,
                                                  const float* __restrict__ xi,
                                                  float2* __restrict__ f) {
    extern __shared__ float2 sm[];
    int t = threadIdx.x & 15, li = threadIdx.x >> 4;
    int line = blockIdx.x * 16 + li;
    int img = line >> 9, y = line & 511, w = img % 3;
    const float2* P = d_expP + ((size_t)w * HH + y) * HH;   // layer 0, natural
    size_t base = (size_t)line * HH;
    float2* pl = sm + li * LPLANE;
    float2 v[32];
#pragma unroll
    for (int a = 0; a < 32; a++) {
        int x = 16 * a + t;
        float2 z = make_float2(xr[base + x], xi[base + x]);
        v[a] = cmulf(z, P[x]);
    }
    gfwd(v, pl, t);
#pragma unroll
    for (int r = 0; r < 32; r++) f[base + 16 * r + t] = v[r];
}

__global__ void __launch_bounds__(256, 2) k_rowmid(float2* __restrict__ f, int layer) {
    extern __shared__ float2 sm[];
    int t = threadIdx.x & 15, li = threadIdx.x >> 4;
    int line = blockIdx.x * 16 + li;
    int img = line >> 9, y = line & 511, w = img % 3;
    const float2* P = d_expP + (((size_t)layer * NWL + w) * HH + y) * HH;
    size_t base = (size_t)line * HH;
    float2* pl = sm + li * LPLANE;
    float2 v[32];
#pragma unroll
    for (int r = 0; r < 32; r++) v[r] = f[base + 16 * r + t];
    ginv(v, pl, t);
#pragma unroll
    for (int a = 0; a < 32; a++) v[a] = cmulf(v[a], P[16 * a + t]);
    gfwd(v, pl, t);
#pragma unroll
    for (int r = 0; r < 32; r++) f[base + 16 * r + t] = v[r];
}

__global__ void __launch_bounds__(256, 2) k_last(float2* __restrict__ f) {
    extern __shared__ float2 sm[];
    int t = threadIdx.x & 15, li = threadIdx.x >> 4;
    int line = blockIdx.x * 16 + li;
    size_t base = (size_t)line * HH;
    float2* pl = sm + li * LPLANE;
    float2 v[32];
#pragma unroll
    for (int r = 0; r < 32; r++) v[r] = f[base + 16 * r + t];
    ginv(v, pl, t);
    const float S = 1.0f / 512.0f;
#pragma unroll
    for (int a = 0; a < 32; a++)
        f[base + 16 * a + t] = make_float2(v[a].x * S, v[a].y * S);
}

// ------- column pass: pipelined tiles, CT=8 cols/tile, 128 threads, double buffer -------
// Block processes TPB consecutive tiles; cp.async stage of tile i+1 overlaps compute of i.

__global__ void __launch_bounds__(128, 3) k_col(float2* __restrict__ f, int det, int rev) {
    extern __shared__ float2 B2[];
    float2* bufs[2] = {B2, B2 + CT * CPLANE};
    int bi = rev ? ((int)gridDim.x - 1 - (int)blockIdx.x) : (int)blockIdx.x;
    int tile0 = bi * TPB;

    int colL = threadIdx.x & 7, rowq = threadIdx.x >> 3;   // stage/drain map: 16 rows x 8 cols
    int g = threadIdx.x >> 4, t = threadIdx.x & 15;        // compute map: 8 groups of 16
    const float2* Htab = det ? d_HLD : d_HL;

    // stage tile 0
    {
        int ti = tile0;
        float2* base = f + (size_t)(ti >> 6) * (HH * HH);
        int c0 = (ti & 63) << 3;
#pragma unroll
        for (int it = 0; it < 32; it++) {
            int r = it * 16 + rowq;
            cpasync8(&bufs[0][colL * CPLANE + r], &base[(size_t)r * HH + c0 + colL]);
        }
        cpcommit();
    }

#pragma unroll 1
    for (int i = 0; i < TPB; i++) {
        int ti = tile0 + i;
        float2* base = f + (size_t)(ti >> 6) * (HH * HH);
        int c0 = (ti & 63) << 3;
        float2* B = bufs[i & 1];

        if (i + 1 < TPB) {                 // stage next tile into other buffer
            int tj = ti + 1;
            float2* nbase = f + (size_t)(tj >> 6) * (HH * HH);
            int nc0 = (tj & 63) << 3;
            float2* NB = bufs[(i + 1) & 1];
#pragma unroll
            for (int it = 0; it < 32; it++) {
                int r = it * 16 + rowq;
                cpasync8(&NB[colL * CPLANE + r], &nbase[(size_t)r * HH + nc0 + colL]);
            }
            cpcommit();
            cpwait1();                     // current tile's group retired
        } else {
            cpwait0();
        }
        __syncthreads();

        float2* pl = B + g * CPLANE;
        float2 v[32];
#pragma unroll
        for (int a = 0; a < 32; a++) v[a] = pl[16 * a + t];
        gfwd(v, pl, t);
        const float2* Hc = Htab + ((size_t)((ti >> 6) % 3) * HH + (c0 + g)) * HH;
#pragma unroll
        for (int r = 0; r < 32; r++) v[r] = cmulf(v[r], Hc[16 * r + t]);
        ginv(v, pl, t);
        __syncwarp();
#pragma unroll
        for (int a = 0; a < 32; a++) pl[16 * a + t] = v[a];
        __syncthreads();

#pragma unroll
        for (int it = 0; it < 32; it++) {
            int r = it * 16 + rowq;
            base[(size_t)r * HH + c0 + colL] = B[colL * CPLANE + r];
        }
        __syncthreads();                   // drain reads complete before buffer reuse
    }
}

// ---------------- launch ----------------
// 11 passes: first | 4x( col(HL), rowmid ) | col(HL*HD merged) | last
extern "C" void kernel_launch(void* const* d_in, const int* in_sizes, int n_in,
                              void* d_out, int out_size) {
    const float* xr = (const float*)d_in[0];
    const float* xi = (const float*)d_in[1];
    const float* pm = (const float*)d_in[2];
    float2* f = (float2*)d_out;

    const int ROWSMEM = 16 * LPLANE * (int)sizeof(float2);      // 67,584 B
    const int COLSMEM = 2 * CT * CPLANE * (int)sizeof(float2);  // 67,712 B (2 buffers)
    cudaFuncSetAttribute(k_first,  cudaFuncAttributeMaxDynamicSharedMemorySize, ROWSMEM);
    cudaFuncSetAttribute(k_rowmid, cudaFuncAttributeMaxDynamicSharedMemorySize, ROWSMEM);
    cudaFuncSetAttribute(k_last,   cudaFuncAttributeMaxDynamicSharedMemorySize, ROWSMEM);
    cudaFuncSetAttribute(k_col,    cudaFuncAttributeMaxDynamicSharedMemorySize, COLSMEM);

    k_initH<<<(NWL * HH * HH + 255) / 256, 256>>>();
    k_initP<<<(NLAY * NWL * HH * HH + 255) / 256, 256>>>(pm);

    const int ROWBLKS = NIMG * HH / 16;              // 2304
    const int COLBLKS = NIMG * (HH / CT) / TPB;      // 1152

    k_first<<<ROWBLKS, 256, ROWSMEM>>>(xr, xi, f);
    for (int l = 0; l < NLAY - 1; l++) {
        k_col<<<COLBLKS, 128, COLSMEM>>>(f, 0, 1);            // HL, reversed
        k_rowmid<<<ROWBLKS, 256, ROWSMEM>>>(f, l + 1);        // forward
    }
    k_col<<<COLBLKS, 128, COLSMEM>>>(f, 1, 1);                // merged HL*HD, reversed
    k_last<<<ROWBLKS, 256, ROWSMEM>>>(f);                     // forward
}

// round 16
// speedup vs baseline: 1.0673x; 1.0673x over previous
#include <cuda_runtime.h>
#include <math.h>

#define HH    512
#define NIMG  72          // B(8)*M(3)*W(3); wavelength = img % 3
#define NWL   3
#define NLAY  5
#define TWO_PI 6.2831853071795864769f

#define LPLANE 528        // row-kernel per-line exchange plane (float2)
#define CPLANE 532        // k_col per-column plane; 532 % 16 == 4 -> conflict-free quad staging

// Storage-slot -> spectral-index map of the 16x32 warp-group FFT.
#define KMAP(s) (((s) & 15) | ((((s) >> 8) & 1) << 4) | ((((s) >> 4) & 15) << 5))

// -------- precomputed tables --------
__device__ float2 d_HL[NWL * HH * HH];    // exp(i kz zL) / 512
__device__ float2 d_HLD[NWL * HH * HH];   // exp(i kz (zL+zD)) / 512 (merged; cancelled pair gain 512)
__device__ float2 d_expP[NLAY * NWL * HH * HH];

__device__ __forceinline__ float2 cmulf(float2 a, float2 b) {
    return make_float2(a.x * b.x - a.y * b.y, a.x * b.y + a.y * b.x);
}
template <int SGN>
__device__ __forceinline__ float2 muli(float2 z) {
    return (SGN > 0) ? make_float2(-z.y, z.x) : make_float2(z.y, -z.x);
}
__device__ __forceinline__ int taud(int k) { return (k < 8) ? 2 * k : 2 * (k - 8) + 1; }
__device__ __forceinline__ int alp(int i) {
    return ((i & 7) << 2) | (((i >> 3) & 1) << 1) | (i >> 4);
}

__device__ __forceinline__ void cpasync8(void* smem, const void* g) {
    unsigned s = (unsigned)__cvta_generic_to_shared(smem);
    asm volatile("cp.async.ca.shared.global [%0], [%1], 8;" :: "r"(s), "l"(g) : "memory");
}
__device__ __forceinline__ void cpcommit() {
    asm volatile("cp.async.commit_group;" ::: "memory");
}
__device__ __forceinline__ void cpwait0() {
    asm volatile("cp.async.wait_group 0;" ::: "memory");
}

// natural-order 8-point DFT (in place)
template <int SGN>
__device__ __forceinline__ void dft8(float2 v[8]) {
    const float C = 0.70710678118654752f;
    const float sg = (float)SGN;
    float2 t0 = make_float2(v[0].x + v[4].x, v[0].y + v[4].y);
    float2 t1 = make_float2(v[0].x - v[4].x, v[0].y - v[4].y);
    float2 t2 = make_float2(v[2].x + v[6].x, v[2].y + v[6].y);
    float2 t3 = make_float2(v[2].x - v[6].x, v[2].y - v[6].y);
    float2 u0 = make_float2(v[1].x + v[5].x, v[1].y + v[5].y);
    float2 u1 = make_float2(v[1].x - v[5].x, v[1].y - v[5].y);
    float2 u2 = make_float2(v[3].x + v[7].x, v[3].y + v[7].y);
    float2 u3 = make_float2(v[3].x - v[7].x, v[3].y - v[7].y);
    float2 it3 = muli<SGN>(t3);
    float2 iu3 = muli<SGN>(u3);
    float2 E0 = make_float2(t0.x + t2.x, t0.y + t2.y);
    float2 E2 = make_float2(t0.x - t2.x, t0.y - t2.y);
    float2 E1 = make_float2(t1.x + it3.x, t1.y + it3.y);
    float2 E3 = make_float2(t1.x - it3.x, t1.y - it3.y);
    float2 O0 = make_float2(u0.x + u2.x, u0.y + u2.y);
    float2 O2 = make_float2(u0.x - u2.x, u0.y - u2.y);
    float2 O1 = make_float2(u1.x + iu3.x, u1.y + iu3.y);
    float2 O3 = make_float2(u1.x - iu3.x, u1.y - iu3.y);
    float2 w1o = make_float2(C * (O1.x - sg * O1.y), C * (O1.y + sg * O1.x));
    float2 w2o = muli<SGN>(O2);
    float2 w3o = make_float2(-C * (O3.x + sg * O3.y), C * (sg * O3.x - O3.y));
    v[0] = make_float2(E0.x + O0.x, E0.y + O0.y);
    v[4] = make_float2(E0.x - O0.x, E0.y - O0.y);
    v[1] = make_float2(E1.x + w1o.x, E1.y + w1o.y);
    v[5] = make_float2(E1.x - w1o.x, E1.y - w1o.y);
    v[2] = make_float2(E2.x + w2o.x, E2.y + w2o.y);
    v[6] = make_float2(E2.x - w2o.x, E2.y - w2o.y);
    v[3] = make_float2(E3.x + w3o.x, E3.y + w3o.y);
    v[7] = make_float2(E3.x - w3o.x, E3.y - w3o.y);
}

#define CC16_1 0.92387953251128674f
#define CC16_2 0.70710678118654752f
#define CC16_3 0.38268343236508977f

template <int SGN>
__device__ __forceinline__ void dit16(float2 v[16]) {
    const float CC[8] = {1.f, CC16_1, CC16_2, CC16_3, 0.f, -CC16_3, -CC16_2, -CC16_1};
    const float SS[8] = {0.f, CC16_3, CC16_2, CC16_1, 1.f, CC16_1, CC16_2, CC16_3};
    dft8<SGN>(v);
    dft8<SGN>(v + 8);
#pragma unroll
    for (int r = 0; r < 8; r++) {
        float2 w = make_float2(CC[r], (float)SGN * SS[r]);
        float2 t = cmulf(v[8 + r], w);
        v[8 + r] = make_float2(v[r].x - t.x, v[r].y - t.y);
        v[r]     = make_float2(v[r].x + t.x, v[r].y + t.y);
    }
}

template <int SGN>
__device__ __forceinline__ void dif16(float2 v[16]) {
    const float CC[8] = {1.f, CC16_1, CC16_2, CC16_3, 0.f, -CC16_3, -CC16_2, -CC16_1};
    const float SS[8] = {0.f, CC16_3, CC16_2, CC16_1, 1.f, CC16_1, CC16_2, CC16_3};
#pragma unroll
    for (int r = 0; r < 8; r++) {
        float2 a = v[r], b = v[8 + r];
        v[r] = make_float2(a.x + b.x, a.y + b.y);
        float2 d = make_float2(a.x - b.x, a.y - b.y);
        float2 w = make_float2(CC[r], (float)SGN * SS[r]);
        v[8 + r] = cmulf(d, w);
    }
    dft8<SGN>(v);
    dft8<SGN>(v + 8);
}

#define C32_1 0.98078528040323044f
#define C32_2 0.92387953251128674f
#define C32_3 0.83146961230254524f
#define C32_4 0.70710678118654752f
#define C32_5 0.55557023301960222f
#define C32_6 0.38268343236508977f
#define C32_7 0.19509032201612827f

template <int SGN>
__device__ __forceinline__ void dit32(float2 v[32]) {
    const float C[16] = {1.f, C32_1, C32_2, C32_3, C32_4, C32_5, C32_6, C32_7,
                         0.f, -C32_7, -C32_6, -C32_5, -C32_4, -C32_3, -C32_2, -C32_1};
    const float S[16] = {0.f, C32_7, C32_6, C32_5, C32_4, C32_3, C32_2, C32_1,
                         1.f, C32_1, C32_2, C32_3, C32_4, C32_5, C32_6, C32_7};
    dit16<SGN>(v);
    dit16<SGN>(v + 16);
#pragma unroll
    for (int r = 0; r < 16; r++) {
        float2 w = make_float2(C[r], (float)SGN * S[r]);
        float2 t = cmulf(v[16 + r], w);
        v[16 + r] = make_float2(v[r].x - t.x, v[r].y - t.y);
        v[r]      = make_float2(v[r].x + t.x, v[r].y + t.y);
    }
}

template <int SGN>
__device__ __forceinline__ void dif32(float2 v[32]) {
    const float C[16] = {1.f, C32_1, C32_2, C32_3, C32_4, C32_5, C32_6, C32_7,
                         0.f, -C32_7, -C32_6, -C32_5, -C32_4, -C32_3, -C32_2, -C32_1};
    const float S[16] = {0.f, C32_7, C32_6, C32_5, C32_4, C32_3, C32_2, C32_1,
                         1.f, C32_1, C32_2, C32_3, C32_4, C32_5, C32_6, C32_7};
#pragma unroll
    for (int r = 0; r < 16; r++) {
        float2 a = v[r], b = v[16 + r];
        v[r] = make_float2(a.x + b.x, a.y + b.y);
        float2 d = make_float2(a.x - b.x, a.y - b.y);
        float2 w = make_float2(C[r], (float)SGN * S[r]);
        v[16 + r] = cmulf(d, w);
    }
    dif16<SGN>(v);
    dif16<SGN>(v + 16);
}

template <int SGN>
__device__ __forceinline__ void twid_alp(float2 v[32], int t) {
    float s, c;
    __sincosf((float)SGN * TWO_PI * (float)t * (1.0f / 512.0f), &s, &c);
    float2 w1 = make_float2(c, s);
    float2 w2 = cmulf(w1, w1);
    float2 w3 = cmulf(w2, w1);
    float2 w4 = cmulf(w2, w2);
    float2 bases[4];
    bases[0] = make_float2(1.f, 0.f); bases[1] = w2; bases[2] = w1; bases[3] = w3;
#pragma unroll
    for (int g = 0; g < 4; g++) {
        float2 tw = bases[g];
#pragma unroll
        for (int k = 0; k < 8; k++) {
            int r = g * 8 + k;
            if (!(g == 0 && k == 0)) v[r] = cmulf(v[r], tw);
            if (k < 7) tw = cmulf(tw, w4);
        }
    }
}

template <int SGN>
__device__ __forceinline__ void twid_tau(float2* v, int m) {
    float s, c;
    __sincosf((float)SGN * TWO_PI * (float)m * (1.0f / 512.0f), &s, &c);
    float2 w1 = make_float2(c, s);
    float2 w2 = cmulf(w1, w1);
    float2 tw = w2;
#pragma unroll
    for (int k = 1; k < 8; k++) { v[k] = cmulf(v[k], tw); tw = cmulf(tw, w2); }
    tw = w1;
#pragma unroll
    for (int k = 8; k < 16; k++) { v[k] = cmulf(v[k], tw); tw = cmulf(tw, w2); }
}

// forward 512-pt group FFT (16 threads, 1 exchange)
__device__ __forceinline__ void gfwd(float2 v[32], float2* pl, int t) {
    dif32<-1>(v);
    twid_alp<-1>(v, t);
    __syncwarp();
#pragma unroll
    for (int r = 0; r < 32; r++) pl[alp(r) + 33 * t] = v[r];
    __syncwarp();
#pragma unroll
    for (int k = 0; k < 16; k++) v[k]      = pl[t      + 33 * taud(k)];
#pragma unroll
    for (int k = 0; k < 16; k++) v[16 + k] = pl[t + 16 + 33 * taud(k)];
    dit16<-1>(v);
    dit16<-1>(v + 16);
}

// inverse 512-pt group FFT (unnormalized)
__device__ __forceinline__ void ginv(float2 v[32], float2* pl, int t) {
    dif16<1>(v);
    dif16<1>(v + 16);
    twid_tau<1>(v, t);
    twid_tau<1>(v + 16, t + 16);
    __syncwarp();
#pragma unroll
    for (int k = 0; k < 16; k++) pl[t      + 33 * taud(k)] = v[k];
#pragma unroll
    for (int k = 0; k < 16; k++) pl[t + 16 + 33 * taud(k)] = v[16 + k];
    __syncwarp();
#pragma unroll
    for (int r = 0; r < 32; r++) v[r] = pl[alp(r) + 33 * t];
    dit32<1>(v);
}

// ---------------- init kernels ----------------

__global__ void __launch_bounds__(256) k_initH() {
    int idx = blockIdx.x * 256 + threadIdx.x;
    if (idx >= NWL * HH * HH) return;
    int w = idx / (HH * HH);
    int xs = (idx >> 9) & 511;
    int j = idx & 511;
    int r = KMAP(xs);
    int c = KMAP(j);
    const float wls[3] = {5.32e-07f, 6.33e-07f, 8.5e-07f};
    const float TW = TWO_PI;
    float mr = (float)((r < 256) ? r : r - 512);
    float mc = (float)((c < 256) ? c : c - 512);
    double invnd = 1.0 / (512.0 * 8e-06);
    float fr = (float)((double)mr * invnd);
    float fc = (float)((double)mc * invnd);
    float kx = __fmul_rn(TW, fr);
    float ky = __fmul_rn(TW, fc);
    float kk = __fdiv_rn(TW, wls[w]);
    float arg = __fsub_rn(__fsub_rn(__fmul_rn(kk, kk), __fmul_rn(kx, kx)),
                          __fmul_rn(ky, ky));
    const float SL  = 1.0f / 512.0f;
    const float SLD = 1.0f / 512.0f;   // merged pass absorbs the cancelled pair's gain 512
    float2 hl, hld;
    if (arg >= 0.0f) {
        float kz = __fsqrt_rn(arg);
        float thL = __fmul_rn(kz, 0.03f);
        float thD = __fmul_rn(kz, 0.1f);
        double sl, cl, sd, cd;
        sincos((double)thL, &sl, &cl);
        sincos((double)thD, &sd, &cd);
        double pr = cl * cd - sl * sd;
        double pi = cl * sd + sl * cd;
        hl  = make_float2((float)cl * SL, (float)sl * SL);
        hld = make_float2((float)pr * SLD, (float)pi * SLD);
    } else {
        float a = __fsqrt_rn(-arg);
        float eL = expf(-__fmul_rn(a, 0.03f));
        float eD = expf(-__fmul_rn(a, 0.1f));
        hl  = make_float2(eL * SL, 0.0f);
        hld = make_float2(eL * eD * SLD, 0.0f);
    }
    d_HL[idx]  = hl;    // arg symmetric in (r,c) => no transpose needed
    d_HLD[idx] = hld;
}

__global__ void __launch_bounds__(256) k_initP(const float* __restrict__ pm) {
    int idx = blockIdx.x * 256 + threadIdx.x;
    if (idx >= NLAY * NWL * HH * HH) return;
    float p = pm[idx];
    float s, c;
    __sincosf(p, &s, &c);
    int layer = idx / (NWL * HH * HH);
    float sc = (layer == 0) ? 1.0f : (1.0f / 512.0f);
    d_expP[idx] = make_float2(c * sc, s * sc);
}

// ---------------- row kernels: 16 threads/line, 16 lines/block ----------------

__global__ void __launch_bounds__(256, 2) k_first(const float* __restrict__ xr,
                                                  const float* __restrict__ xi,
                                                  float2* __restrict__ f) {
    extern __shared__ float2 sm[];
    int t = threadIdx.x & 15, li = threadIdx.x >> 4;
    int line = blockIdx.x * 16 + li;
    int img = line >> 9, y = line & 511, w = img % 3;
    const float2* P = d_expP + ((size_t)w * HH + y) * HH;   // layer 0, natural
    size_t base = (size_t)line * HH;
    float2* pl = sm + li * LPLANE;
    float2 v[32];
#pragma unroll
    for (int a = 0; a < 32; a++) {
        int x = 16 * a + t;
        float2 z = make_float2(xr[base + x], xi[base + x]);
        v[a] = cmulf(z, P[x]);
    }
    gfwd(v, pl, t);
#pragma unroll
    for (int r = 0; r < 32; r++) f[base + 16 * r + t] = v[r];
}

__global__ void __launch_bounds__(256, 2) k_rowmid(float2* __restrict__ f, int layer) {
    extern __shared__ float2 sm[];
    int t = threadIdx.x & 15, li = threadIdx.x >> 4;
    int line = blockIdx.x * 16 + li;
    int img = line >> 9, y = line & 511, w = img % 3;
    const float2* P = d_expP + (((size_t)layer * NWL + w) * HH + y) * HH;
    size_t base = (size_t)line * HH;
    float2* pl = sm + li * LPLANE;
    float2 v[32];
#pragma unroll
    for (int r = 0; r < 32; r++) v[r] = f[base + 16 * r + t];
    ginv(v, pl, t);
#pragma unroll
    for (int a = 0; a < 32; a++) v[a] = cmulf(v[a], P[16 * a + t]);
    gfwd(v, pl, t);
#pragma unroll
    for (int r = 0; r < 32; r++) f[base + 16 * r + t] = v[r];
}

__global__ void __launch_bounds__(256, 2) k_last(float2* __restrict__ f) {
    extern __shared__ float2 sm[];
    int t = threadIdx.x & 15, li = threadIdx.x >> 4;
    int line = blockIdx.x * 16 + li;
    size_t base = (size_t)line * HH;
    float2* pl = sm + li * LPLANE;
    float2 v[32];
#pragma unroll
    for (int r = 0; r < 32; r++) v[r] = f[base + 16 * r + t];
    ginv(v, pl, t);
    const float S = 1.0f / 512.0f;
#pragma unroll
    for (int a = 0; a < 32; a++)
        f[base + 16 * a + t] = make_float2(v[a].x * S, v[a].y * S);
}

// ------- column pass: per-warp autonomous, 4 cols/warp (full-sector), no block barriers -------
// 128 threads = 4 warps; block covers 16 columns. Warp stages its 4 columns via cp.async
// (4 lanes x 8B = one 32B sector per row), waits its own group, computes 2 FFT chains per
// 16-thread group, writes back, drains. No __syncthreads anywhere.

__global__ void __launch_bounds__(128, 3) k_col(float2* __restrict__ f, int det, int rev) {
    extern __shared__ float2 T[];
    int bi = rev ? ((int)gridDim.x - 1 - (int)blockIdx.x) : (int)blockIdx.x;
    int img = bi >> 5;                       // 32 tiles per image
    int c0 = (bi & 31) << 4;
    int w = img % 3;
    float2* base = f + (size_t)img * (HH * HH);

    int wid = threadIdx.x >> 5;              // warp owns cols c0 + 4*wid .. +3
    int lane = threadIdx.x & 31;
    int cq = lane & 3;                       // column within quad
    int r8 = lane >> 2;                      // 0..7 row slice
    int myc = 4 * wid + cq;
    float2* gcol = base + c0 + myc;
    float2* mpl = T + myc * CPLANE;

    // stage: 64 iters x 8 rows; each row covered by 4 contiguous lanes (32B sector)
#pragma unroll 8
    for (int it = 0; it < 64; it++) {
        int r = it * 8 + r8;
        cpasync8(&mpl[r], &gcol[(size_t)r * HH]);
    }
    cpcommit();
    cpwait0();
    __syncwarp();

    int g2 = lane >> 4, t = lane & 15;       // two 16-thread groups per warp
    const float2* Htab = det ? d_HLD : d_HL;
#pragma unroll 1
    for (int j = 0; j < 2; j++) {
        int cp = 4 * wid + 2 * g2 + j;       // group g2 computes cols {4w+2g2, 4w+2g2+1}
        float2* pl = T + cp * CPLANE;
        float2 v[32];
#pragma unroll
        for (int a = 0; a < 32; a++) v[a] = pl[16 * a + t];
        gfwd(v, pl, t);
        const float2* Hc = Htab + ((size_t)w * HH + (c0 + cp)) * HH;
#pragma unroll
        for (int r = 0; r < 32; r++) v[r] = cmulf(v[r], Hc[16 * r + t]);
        ginv(v, pl, t);
        __syncwarp();
#pragma unroll
        for (int a = 0; a < 32; a++) pl[16 * a + t] = v[a];
        __syncwarp();
    }

    // drain: same sector-coalesced mapping
#pragma unroll 8
    for (int it = 0; it < 64; it++) {
        int r = it * 8 + r8;
        gcol[(size_t)r * HH] = mpl[r];
    }
}

// ---------------- launch ----------------
// 11 passes: first | 4x( col(HL), rowmid ) | col(HL*HD merged) | last
extern "C" void kernel_launch(void* const* d_in, const int* in_sizes, int n_in,
                              void* d_out, int out_size) {
    const float* xr = (const float*)d_in[0];
    const float* xi = (const float*)d_in[1];
    const float* pm = (const float*)d_in[2];
    float2* f = (float2*)d_out;

    const int ROWSMEM = 16 * LPLANE * (int)sizeof(float2);   // 67,584 B
    const int COLSMEM = 16 * CPLANE * (int)sizeof(float2);   // 68,096 B
    cudaFuncSetAttribute(k_first,  cudaFuncAttributeMaxDynamicSharedMemorySize, ROWSMEM);
    cudaFuncSetAttribute(k_rowmid, cudaFuncAttributeMaxDynamicSharedMemorySize, ROWSMEM);
    cudaFuncSetAttribute(k_last,   cudaFuncAttributeMaxDynamicSharedMemorySize, ROWSMEM);
    cudaFuncSetAttribute(k_col,    cudaFuncAttributeMaxDynamicSharedMemorySize, COLSMEM);

    k_initH<<<(NWL * HH * HH + 255) / 256, 256>>>();
    k_initP<<<(NLAY * NWL * HH * HH + 255) / 256, 256>>>(pm);

    const int ROWBLKS = NIMG * HH / 16;        // 2304
    const int COLBLKS = NIMG * (HH / 16);      // 2304

    k_first<<<ROWBLKS, 256, ROWSMEM>>>(xr, xi, f);
    for (int l = 0; l < NLAY - 1; l++) {
        k_col<<<COLBLKS, 128, COLSMEM>>>(f, 0, 1);            // HL, reversed
        k_rowmid<<<ROWBLKS, 256, ROWSMEM>>>(f, l + 1);        // forward
    }
    k_col<<<COLBLKS, 128, COLSMEM>>>(f, 1, 1);                // merged HL*HD, reversed
    k_last<<<ROWBLKS, 256, ROWSMEM>>>(f);                     // forward
}

// round 17
// speedup vs baseline: 1.1976x; 1.1221x over previous
#include <cuda_runtime.h>
#include <math.h>

#define HH    512
#define NIMG  72          // B(8)*M(3)*W(3); wavelength = img % 3
#define NWL   3
#define NLAY  5
#define TWO_PI 6.2831853071795864769f

#define LPLANE 528        // row-kernel per-line exchange plane (float2)
#define CPLANE 529        // k_col per-column plane (odd float2 stride)
#define CT     8          // columns per k_col block (128 threads, 4 blocks/SM)

// Storage-slot -> spectral-index map of the 16x32 warp-group FFT.
#define KMAP(s) (((s) & 15) | ((((s) >> 8) & 1) << 4) | ((((s) >> 4) & 15) << 5))

// -------- precomputed tables --------
__device__ float2 d_HL[NWL * HH * HH];    // exp(i kz zL) / 512
__device__ float2 d_HLD[NWL * HH * HH];   // exp(i kz (zL+zD)) / 512 (merged; cancelled pair gain 512)
__device__ float2 d_expP[NLAY * NWL * HH * HH];

__device__ __forceinline__ float2 cmulf(float2 a, float2 b) {
    return make_float2(a.x * b.x - a.y * b.y, a.x * b.y + a.y * b.x);
}
template <int SGN>
__device__ __forceinline__ float2 muli(float2 z) {
    return (SGN > 0) ? make_float2(-z.y, z.x) : make_float2(z.y, -z.x);
}
__device__ __forceinline__ int taud(int k) { return (k < 8) ? 2 * k : 2 * (k - 8) + 1; }
__device__ __forceinline__ int alp(int i) {
    return ((i & 7) << 2) | (((i >> 3) & 1) << 1) | (i >> 4);
}

__device__ __forceinline__ void cpasync8(void* smem, const void* g) {
    unsigned s = (unsigned)__cvta_generic_to_shared(smem);
    asm volatile("cp.async.ca.shared.global [%0], [%1], 8;" :: "r"(s), "l"(g) : "memory");
}
__device__ __forceinline__ void cpcommit() {
    asm volatile("cp.async.commit_group;" ::: "memory");
}
__device__ __forceinline__ void cpwait0() {
    asm volatile("cp.async.wait_group 0;" ::: "memory");
}

// natural-order 8-point DFT (in place)
template <int SGN>
__device__ __forceinline__ void dft8(float2 v[8]) {
    const float C = 0.70710678118654752f;
    const float sg = (float)SGN;
    float2 t0 = make_float2(v[0].x + v[4].x, v[0].y + v[4].y);
    float2 t1 = make_float2(v[0].x - v[4].x, v[0].y - v[4].y);
    float2 t2 = make_float2(v[2].x + v[6].x, v[2].y + v[6].y);
    float2 t3 = make_float2(v[2].x - v[6].x, v[2].y - v[6].y);
    float2 u0 = make_float2(v[1].x + v[5].x, v[1].y + v[5].y);
    float2 u1 = make_float2(v[1].x - v[5].x, v[1].y - v[5].y);
    float2 u2 = make_float2(v[3].x + v[7].x, v[3].y + v[7].y);
    float2 u3 = make_float2(v[3].x - v[7].x, v[3].y - v[7].y);
    float2 it3 = muli<SGN>(t3);
    float2 iu3 = muli<SGN>(u3);
    float2 E0 = make_float2(t0.x + t2.x, t0.y + t2.y);
    float2 E2 = make_float2(t0.x - t2.x, t0.y - t2.y);
    float2 E1 = make_float2(t1.x + it3.x, t1.y + it3.y);
    float2 E3 = make_float2(t1.x - it3.x, t1.y - it3.y);
    float2 O0 = make_float2(u0.x + u2.x, u0.y + u2.y);
    float2 O2 = make_float2(u0.x - u2.x, u0.y - u2.y);
    float2 O1 = make_float2(u1.x + iu3.x, u1.y + iu3.y);
    float2 O3 = make_float2(u1.x - iu3.x, u1.y - iu3.y);
    float2 w1o = make_float2(C * (O1.x - sg * O1.y), C * (O1.y + sg * O1.x));
    float2 w2o = muli<SGN>(O2);
    float2 w3o = make_float2(-C * (O3.x + sg * O3.y), C * (sg * O3.x - O3.y));
    v[0] = make_float2(E0.x + O0.x, E0.y + O0.y);
    v[4] = make_float2(E0.x - O0.x, E0.y - O0.y);
    v[1] = make_float2(E1.x + w1o.x, E1.y + w1o.y);
    v[5] = make_float2(E1.x - w1o.x, E1.y - w1o.y);
    v[2] = make_float2(E2.x + w2o.x, E2.y + w2o.y);
    v[6] = make_float2(E2.x - w2o.x, E2.y - w2o.y);
    v[3] = make_float2(E3.x + w3o.x, E3.y + w3o.y);
    v[7] = make_float2(E3.x - w3o.x, E3.y - w3o.y);
}

#define CC16_1 0.92387953251128674f
#define CC16_2 0.70710678118654752f
#define CC16_3 0.38268343236508977f

template <int SGN>
__device__ __forceinline__ void dit16(float2 v[16]) {
    const float CC[8] = {1.f, CC16_1, CC16_2, CC16_3, 0.f, -CC16_3, -CC16_2, -CC16_1};
    const float SS[8] = {0.f, CC16_3, CC16_2, CC16_1, 1.f, CC16_1, CC16_2, CC16_3};
    dft8<SGN>(v);
    dft8<SGN>(v + 8);
#pragma unroll
    for (int r = 0; r < 8; r++) {
        float2 w = make_float2(CC[r], (float)SGN * SS[r]);
        float2 t = cmulf(v[8 + r], w);
        v[8 + r] = make_float2(v[r].x - t.x, v[r].y - t.y);
        v[r]     = make_float2(v[r].x + t.x, v[r].y + t.y);
    }
}

template <int SGN>
__device__ __forceinline__ void dif16(float2 v[16]) {
    const float CC[8] = {1.f, CC16_1, CC16_2, CC16_3, 0.f, -CC16_3, -CC16_2, -CC16_1};
    const float SS[8] = {0.f, CC16_3, CC16_2, CC16_1, 1.f, CC16_1, CC16_2, CC16_3};
#pragma unroll
    for (int r = 0; r < 8; r++) {
        float2 a = v[r], b = v[8 + r];
        v[r] = make_float2(a.x + b.x, a.y + b.y);
        float2 d = make_float2(a.x - b.x, a.y - b.y);
        float2 w = make_float2(CC[r], (float)SGN * SS[r]);
        v[8 + r] = cmulf(d, w);
    }
    dft8<SGN>(v);
    dft8<SGN>(v + 8);
}

#define C32_1 0.98078528040323044f
#define C32_2 0.92387953251128674f
#define C32_3 0.83146961230254524f
#define C32_4 0.70710678118654752f
#define C32_5 0.55557023301960222f
#define C32_6 0.38268343236508977f
#define C32_7 0.19509032201612827f

template <int SGN>
__device__ __forceinline__ void dit32(float2 v[32]) {
    const float C[16] = {1.f, C32_1, C32_2, C32_3, C32_4, C32_5, C32_6, C32_7,
                         0.f, -C32_7, -C32_6, -C32_5, -C32_4, -C32_3, -C32_2, -C32_1};
    const float S[16] = {0.f, C32_7, C32_6, C32_5, C32_4, C32_3, C32_2, C32_1,
                         1.f, C32_1, C32_2, C32_3, C32_4, C32_5, C32_6, C32_7};
    dit16<SGN>(v);
    dit16<SGN>(v + 16);
#pragma unroll
    for (int r = 0; r < 16; r++) {
        float2 w = make_float2(C[r], (float)SGN * S[r]);
        float2 t = cmulf(v[16 + r], w);
        v[16 + r] = make_float2(v[r].x - t.x, v[r].y - t.y);
        v[r]      = make_float2(v[r].x + t.x, v[r].y + t.y);
    }
}

template <int SGN>
__device__ __forceinline__ void dif32(float2 v[32]) {
    const float C[16] = {1.f, C32_1, C32_2, C32_3, C32_4, C32_5, C32_6, C32_7,
                         0.f, -C32_7, -C32_6, -C32_5, -C32_4, -C32_3, -C32_2, -C32_1};
    const float S[16] = {0.f, C32_7, C32_6, C32_5, C32_4, C32_3, C32_2, C32_1,
                         1.f, C32_1, C32_2, C32_3, C32_4, C32_5, C32_6, C32_7};
#pragma unroll
    for (int r = 0; r < 16; r++) {
        float2 a = v[r], b = v[16 + r];
        v[r] = make_float2(a.x + b.x, a.y + b.y);
        float2 d = make_float2(a.x - b.x, a.y - b.y);
        float2 w = make_float2(C[r], (float)SGN * S[r]);
        v[16 + r] = cmulf(d, w);
    }
    dif16<SGN>(v);
    dif16<SGN>(v + 16);
}

template <int SGN>
__device__ __forceinline__ void twid_alp(float2 v[32], int t) {
    float s, c;
    __sincosf((float)SGN * TWO_PI * (float)t * (1.0f / 512.0f), &s, &c);
    float2 w1 = make_float2(c, s);
    float2 w2 = cmulf(w1, w1);
    float2 w3 = cmulf(w2, w1);
    float2 w4 = cmulf(w2, w2);
    float2 bases[4];
    bases[0] = make_float2(1.f, 0.f); bases[1] = w2; bases[2] = w1; bases[3] = w3;
#pragma unroll
    for (int g = 0; g < 4; g++) {
        float2 tw = bases[g];
#pragma unroll
        for (int k = 0; k < 8; k++) {
            int r = g * 8 + k;
            if (!(g == 0 && k == 0)) v[r] = cmulf(v[r], tw);
            if (k < 7) tw = cmulf(tw, w4);
        }
    }
}

template <int SGN>
__device__ __forceinline__ void twid_tau(float2* v, int m) {
    float s, c;
    __sincosf((float)SGN * TWO_PI * (float)m * (1.0f / 512.0f), &s, &c);
    float2 w1 = make_float2(c, s);
    float2 w2 = cmulf(w1, w1);
    float2 tw = w2;
#pragma unroll
    for (int k = 1; k < 8; k++) { v[k] = cmulf(v[k], tw); tw = cmulf(tw, w2); }
    tw = w1;
#pragma unroll
    for (int k = 8; k < 16; k++) { v[k] = cmulf(v[k], tw); tw = cmulf(tw, w2); }
}

// forward 512-pt group FFT (16 threads, 1 exchange)
__device__ __forceinline__ void gfwd(float2 v[32], float2* pl, int t) {
    dif32<-1>(v);
    twid_alp<-1>(v, t);
    __syncwarp();
#pragma unroll
    for (int r = 0; r < 32; r++) pl[alp(r) + 33 * t] = v[r];
    __syncwarp();
#pragma unroll
    for (int k = 0; k < 16; k++) v[k]      = pl[t      + 33 * taud(k)];
#pragma unroll
    for (int k = 0; k < 16; k++) v[16 + k] = pl[t + 16 + 33 * taud(k)];
    dit16<-1>(v);
    dit16<-1>(v + 16);
}

// inverse 512-pt group FFT (unnormalized)
__device__ __forceinline__ void ginv(float2 v[32], float2* pl, int t) {
    dif16<1>(v);
    dif16<1>(v + 16);
    twid_tau<1>(v, t);
    twid_tau<1>(v + 16, t + 16);
    __syncwarp();
#pragma unroll
    for (int k = 0; k < 16; k++) pl[t      + 33 * taud(k)] = v[k];
#pragma unroll
    for (int k = 0; k < 16; k++) pl[t + 16 + 33 * taud(k)] = v[16 + k];
    __syncwarp();
#pragma unroll
    for (int r = 0; r < 32; r++) v[r] = pl[alp(r) + 33 * t];
    dit32<1>(v);
}

// ---------------- init kernels ----------------

__global__ void __launch_bounds__(256) k_initH() {
    int idx = blockIdx.x * 256 + threadIdx.x;
    if (idx >= NWL * HH * HH) return;
    int w = idx / (HH * HH);
    int xs = (idx >> 9) & 511;
    int j = idx & 511;
    int r = KMAP(xs);
    int c = KMAP(j);
    const float wls[3] = {5.32e-07f, 6.33e-07f, 8.5e-07f};
    const float TW = TWO_PI;
    float mr = (float)((r < 256) ? r : r - 512);
    float mc = (float)((c < 256) ? c : c - 512);
    double invnd = 1.0 / (512.0 * 8e-06);
    float fr = (float)((double)mr * invnd);
    float fc = (float)((double)mc * invnd);
    float kx = __fmul_rn(TW, fr);
    float ky = __fmul_rn(TW, fc);
    float kk = __fdiv_rn(TW, wls[w]);
    float arg = __fsub_rn(__fsub_rn(__fmul_rn(kk, kk), __fmul_rn(kx, kx)),
                          __fmul_rn(ky, ky));
    const float SL  = 1.0f / 512.0f;
    const float SLD = 1.0f / 512.0f;   // merged pass absorbs the cancelled pair's gain 512
    float2 hl, hld;
    if (arg >= 0.0f) {
        float kz = __fsqrt_rn(arg);
        float thL = __fmul_rn(kz, 0.03f);
        float thD = __fmul_rn(kz, 0.1f);
        double sl, cl, sd, cd;
        sincos((double)thL, &sl, &cl);
        sincos((double)thD, &sd, &cd);
        double pr = cl * cd - sl * sd;
        double pi = cl * sd + sl * cd;
        hl  = make_float2((float)cl * SL, (float)sl * SL);
        hld = make_float2((float)pr * SLD, (float)pi * SLD);
    } else {
        float a = __fsqrt_rn(-arg);
        float eL = expf(-__fmul_rn(a, 0.03f));
        float eD = expf(-__fmul_rn(a, 0.1f));
        hl  = make_float2(eL * SL, 0.0f);
        hld = make_float2(eL * eD * SLD, 0.0f);
    }
    d_HL[idx]  = hl;    // arg symmetric in (r,c) => no transpose needed
    d_HLD[idx] = hld;
}

__global__ void __launch_bounds__(256) k_initP(const float* __restrict__ pm) {
    int idx = blockIdx.x * 256 + threadIdx.x;
    if (idx >= NLAY * NWL * HH * HH) return;
    float p = pm[idx];
    float s, c;
    __sincosf(p, &s, &c);
    int layer = idx / (NWL * HH * HH);
    float sc = (layer == 0) ? 1.0f : (1.0f / 512.0f);
    d_expP[idx] = make_float2(c * sc, s * sc);
}

// ---------------- row kernels: 16 threads/line, 16 lines/block ----------------

__global__ void __launch_bounds__(256, 2) k_first(const float* __restrict__ xr,
                                                  const float* __restrict__ xi,
                                                  float2* __restrict__ f) {
    extern __shared__ float2 sm[];
    int t = threadIdx.x & 15, li = threadIdx.x >> 4;
    int line = blockIdx.x * 16 + li;
    int img = line >> 9, y = line & 511, w = img % 3;
    const float2* P = d_expP + ((size_t)w * HH + y) * HH;   // layer 0, natural
    size_t base = (size_t)line * HH;
    float2* pl = sm + li * LPLANE;
    float2 v[32];
#pragma unroll
    for (int a = 0; a < 32; a++) {
        int x = 16 * a + t;
        float2 z = make_float2(xr[base + x], xi[base + x]);
        v[a] = cmulf(z, P[x]);
    }
    gfwd(v, pl, t);
#pragma unroll
    for (int r = 0; r < 32; r++) f[base + 16 * r + t] = v[r];
}

__global__ void __launch_bounds__(256, 2) k_rowmid(float2* __restrict__ f, int layer) {
    extern __shared__ float2 sm[];
    int t = threadIdx.x & 15, li = threadIdx.x >> 4;
    int line = blockIdx.x * 16 + li;
    int img = line >> 9, y = line & 511, w = img % 3;
    const float2* P = d_expP + (((size_t)layer * NWL + w) * HH + y) * HH;
    size_t base = (size_t)line * HH;
    float2* pl = sm + li * LPLANE;
    float2 v[32];
#pragma unroll
    for (int r = 0; r < 32; r++) v[r] = f[base + 16 * r + t];
    ginv(v, pl, t);
#pragma unroll
    for (int a = 0; a < 32; a++) v[a] = cmulf(v[a], P[16 * a + t]);
    gfwd(v, pl, t);
#pragma unroll
    for (int r = 0; r < 32; r++) f[base + 16 * r + t] = v[r];
}

__global__ void __launch_bounds__(256, 2) k_last(float2* __restrict__ f) {
    extern __shared__ float2 sm[];
    int t = threadIdx.x & 15, li = threadIdx.x >> 4;
    int line = blockIdx.x * 16 + li;
    size_t base = (size_t)line * HH;
    float2* pl = sm + li * LPLANE;
    float2 v[32];
#pragma unroll
    for (int r = 0; r < 32; r++) v[r] = f[base + 16 * r + t];
    ginv(v, pl, t);
    const float S = 1.0f / 512.0f;
#pragma unroll
    for (int a = 0; a < 32; a++)
        f[base + 16 * a + t] = make_float2(v[a].x * S, v[a].y * S);
}

// ------- column pass: CT=8 cols/block, 128 threads, 4 blocks/SM (R9 measured-best form) -------

__global__ void __launch_bounds__(128, 4) k_col(float2* __restrict__ f, int det, int rev) {
    extern __shared__ float2 T[];
    int bi = rev ? ((int)gridDim.x - 1 - (int)blockIdx.x) : (int)blockIdx.x;
    int img = bi >> 6;                       // 64 tiles per image
    int c0 = (bi & 63) << 3;
    int w = img % 3;
    float2* base = f + (size_t)img * (HH * HH);

    int colL = threadIdx.x & 7, rowq = threadIdx.x >> 3;   // 16 rows x 8 cols per iter
#pragma unroll
    for (int it = 0; it < 32; it++) {
        int r = it * 16 + rowq;
        cpasync8(&T[colL * CPLANE + r], &base[(size_t)r * HH + c0 + colL]);
    }
    cpcommit();
    cpwait0();
    __syncthreads();

    int g = threadIdx.x >> 4, t = threadIdx.x & 15;        // 8 groups of 16
    float2* pl = T + g * CPLANE;
    float2 v[32];
#pragma unroll
    for (int a = 0; a < 32; a++) v[a] = pl[16 * a + t];
    gfwd(v, pl, t);
    const float2* Hc = (det ? d_HLD : d_HL) + ((size_t)w * HH + (c0 + g)) * HH;
#pragma unroll
    for (int r = 0; r < 32; r++) v[r] = cmulf(v[r], Hc[16 * r + t]);
    ginv(v, pl, t);
    __syncwarp();
#pragma unroll
    for (int a = 0; a < 32; a++) pl[16 * a + t] = v[a];
    __syncthreads();

#pragma unroll
    for (int it = 0; it < 32; it++) {
        int r = it * 16 + rowq;
        base[(size_t)r * HH + c0 + colL] = T[colL * CPLANE + r];
    }
}

// ---------------- launch ----------------
// 11 passes: first | 4x( col(HL), rowmid ) | col(HL*HD merged) | last
extern "C" void kernel_launch(void* const* d_in, const int* in_sizes, int n_in,
                              void* d_out, int out_size) {
    const float* xr = (const float*)d_in[0];
    const float* xi = (const float*)d_in[1];
    const float* pm = (const float*)d_in[2];
    float2* f = (float2*)d_out;

    const int ROWSMEM = 16 * LPLANE * (int)sizeof(float2);   // 67,584 B
    const int COLSMEM = CT * CPLANE * (int)sizeof(float2);   // 33,856 B
    cudaFuncSetAttribute(k_first,  cudaFuncAttributeMaxDynamicSharedMemorySize, ROWSMEM);
    cudaFuncSetAttribute(k_rowmid, cudaFuncAttributeMaxDynamicSharedMemorySize, ROWSMEM);
    cudaFuncSetAttribute(k_last,   cudaFuncAttributeMaxDynamicSharedMemorySize, ROWSMEM);
    cudaFuncSetAttribute(k_col,    cudaFuncAttributeMaxDynamicSharedMemorySize, COLSMEM);

    k_initH<<<(NWL * HH * HH + 255) / 256, 256>>>();
    k_initP<<<(NLAY * NWL * HH * HH + 255) / 256, 256>>>(pm);

    const int ROWBLKS = NIMG * HH / 16;        // 2304
    const int COLBLKS = NIMG * (HH / CT);      // 4608

    k_first<<<ROWBLKS, 256, ROWSMEM>>>(xr, xi, f);
    for (int l = 0; l < NLAY - 1; l++) {
        k_col<<<COLBLKS, 128, COLSMEM>>>(f, 0, 1);            // HL, reversed
        k_rowmid<<<ROWBLKS, 256, ROWSMEM>>>(f, l + 1);        // forward
    }
    k_col<<<COLBLKS, 128, COLSMEM>>>(f, 1, 1);                // merged HL*HD, reversed
    k_last<<<ROWBLKS, 256, ROWSMEM>>>(f);                     // forward
}